// round 1
// baseline (speedup 1.0000x reference)
#include <cuda_runtime.h>
#include <math.h>

#define NN 10000
#define NE 160000

// ---------------- device scratch (no allocations allowed) ----------------
__device__ int   g_count;
__device__ int   g_ei[NE];
__device__ int   g_ej[NE];
__device__ float g_env[NE];
__device__ float g_unit[NE * 3];
__device__ float g_rbf[NE * 20];
__device__ float g_h[NN * 128];
__device__ float g_phi[NN * 384];
__device__ float g_vz[NN * 384];
__device__ float g_va[NN * 384];
__device__ float g_vb[NN * 384];

__device__ __forceinline__ void red4(float* a, float x, float y, float z, float w) {
    asm volatile("red.global.add.v4.f32 [%0], {%1,%2,%3,%4};"
                 :: "l"(a), "f"(x), "f"(y), "f"(z), "f"(w) : "memory");
}

// ---------------- per-edge geometry + RBF precompute (with compaction) ----
__global__ void precompute_kernel(const float* __restrict__ xyz,
                                  const int* __restrict__ nbr) {
    int e = blockIdx.x * blockDim.x + threadIdx.x;
    bool active = false;
    int ni = 0, nj = 0;
    float rx = 0.f, ry = 0.f, rz = 0.f, dist = 1.f;
    if (e < NE) {
        ni = nbr[2 * e]; nj = nbr[2 * e + 1];
        float x0 = xyz[3 * ni], x1 = xyz[3 * ni + 1], x2 = xyz[3 * ni + 2];
        rx = xyz[3 * nj]     - x0;
        ry = xyz[3 * nj + 1] - x1;
        rz = xyz[3 * nj + 2] - x2;
        dist = sqrtf(rx * rx + ry * ry + rz * rz + 3e-15f);
        active = (dist < 5.0f);   // env==0 edges contribute nothing: drop them
    }
    unsigned mask = __ballot_sync(0xffffffffu, active);
    if (!active) return;
    int lane = threadIdx.x & 31;
    int rank = __popc(mask & ((1u << lane) - 1u));
    int leader = __ffs((int)mask) - 1;
    int base = 0;
    if (lane == leader) base = atomicAdd(&g_count, __popc(mask));
    base = __shfl_sync(mask, base, leader);
    int pos = base + rank;

    float inv = 1.0f / dist;
    g_ei[pos] = ni; g_ej[pos] = nj;
    g_unit[3 * pos]     = rx * inv;
    g_unit[3 * pos + 1] = ry * inv;
    g_unit[3 * pos + 2] = rz * inv;
    g_env[pos] = 0.5f * (cosf(dist * 0.6283185307179586f) + 1.0f);

    // rbf[k] = exp(-beta*(exp(-d)-mu_k)^2), mu_k = mu0 + k*delta (linspace)
    // factored: rbf[k] = A * t^k * s1^(k^2)  -> multiplicative recurrence
    const float MU0   = 0.006737946999085467f;   // exp(-5)
    const float DELTA = 0.05227695015794287f;    // (1-exp(-5))/19
    const float BETA  = 101.3613328f;            // (0.1*(1-exp(-5)))^-2
    float x  = expf(-dist);
    float u  = x - MU0;
    float a0 = expf(-BETA * u * u);
    float t  = expf(2.0f * BETA * DELTA * u);
    float s1 = expf(-BETA * DELTA * DELTA);
    float s2 = s1 * s1;
    float val = a0;
    float f = t * s1;
    #pragma unroll
    for (int k = 0; k < 20; k++) {
        g_rbf[20 * pos + k] = val;
        val *= f;
        f *= s2;
    }
}

// ---------------- fp32 SGEMM, K=128 fixed: C = act(A@B + bias) -------------
template<int ACT>
__global__ void __launch_bounds__(256)
gemm_k128(const float* __restrict__ A, const float* __restrict__ B,
          const float* __restrict__ bias, float* __restrict__ C,
          int M, int N) {
    __shared__ float As[32][132];
    __shared__ float Bs[32][132];
    int tid = threadIdx.x;
    int tx = tid & 15, ty = tid >> 4;
    int brow = blockIdx.x * 128;
    int bcol = blockIdx.y * 128;
    float acc[8][8];
    #pragma unroll
    for (int i = 0; i < 8; i++)
        #pragma unroll
        for (int j = 0; j < 8; j++) acc[i][j] = 0.f;

    for (int kt = 0; kt < 4; kt++) {
        #pragma unroll
        for (int r = 0; r < 16; r++) {
            int lin = tid + 256 * r;
            int m = lin >> 5, k = lin & 31;
            int gm = brow + m;
            As[k][m] = (gm < M) ? A[gm * 128 + kt * 32 + k] : 0.f;
        }
        #pragma unroll
        for (int r = 0; r < 16; r++) {
            int lin = tid + 256 * r;
            int k = lin >> 7, n = lin & 127;
            Bs[k][n] = B[(kt * 32 + k) * N + bcol + n];
        }
        __syncthreads();
        #pragma unroll
        for (int k = 0; k < 32; k++) {
            float4 a0 = *reinterpret_cast<const float4*>(&As[k][ty * 8]);
            float4 a1 = *reinterpret_cast<const float4*>(&As[k][ty * 8 + 4]);
            float4 b0 = *reinterpret_cast<const float4*>(&Bs[k][tx * 8]);
            float4 b1 = *reinterpret_cast<const float4*>(&Bs[k][tx * 8 + 4]);
            float av[8] = {a0.x, a0.y, a0.z, a0.w, a1.x, a1.y, a1.z, a1.w};
            float bv[8] = {b0.x, b0.y, b0.z, b0.w, b1.x, b1.y, b1.z, b1.w};
            #pragma unroll
            for (int i = 0; i < 8; i++)
                #pragma unroll
                for (int j = 0; j < 8; j++)
                    acc[i][j] += av[i] * bv[j];
        }
        __syncthreads();
    }
    float bv[8];
    #pragma unroll
    for (int j = 0; j < 8; j++) bv[j] = bias[bcol + tx * 8 + j];
    #pragma unroll
    for (int i = 0; i < 8; i++) {
        int row = brow + ty * 8 + i;
        if (row < M) {
            float o[8];
            #pragma unroll
            for (int j = 0; j < 8; j++) {
                float c = acc[i][j] + bv[j];
                if (ACT) c = c / (1.0f + expf(-c));   // silu
                o[j] = c;
            }
            float4* dst = reinterpret_cast<float4*>(&C[row * N + bcol + tx * 8]);
            dst[0] = make_float4(o[0], o[1], o[2], o[3]);
            dst[1] = make_float4(o[4], o[5], o[6], o[7]);
        }
    }
}

// ---------------- edge kernel: w_s, prod, scatter (v4 atomics) -------------
__global__ void __launch_bounds__(128)
edge_kernel(const float* __restrict__ phi, const float* __restrict__ v_in,
            float* __restrict__ s_acc, float* __restrict__ v_acc,
            const float* __restrict__ Wr, const float* __restrict__ brv) {
    __shared__ float rbf_s[8 * 20];
    __shared__ float unit_s[24];
    __shared__ float env_s[8];
    __shared__ int   ii_s[8];
    __shared__ int   jj_s[8];
    __shared__ float prod_s[8 * 512];
    int t = threadIdx.x;

    // Wr columns for features {t, 128+t, 256+t} live in registers
    float wr[60];
    #pragma unroll
    for (int k = 0; k < 20; k++) {
        wr[k]      = Wr[k * 384 + t];
        wr[20 + k] = Wr[k * 384 + 128 + t];
        wr[40 + k] = Wr[k * 384 + 256 + t];
    }
    float br0 = brv[t], br1 = brv[128 + t], br2 = brv[256 + t];

    int count = g_count;
    int ntiles = (count + 7) >> 3;
    for (int tile = blockIdx.x; tile < ntiles; tile += gridDim.x) {
        int e0 = tile << 3;
        int emax = min(8, count - e0);
        if (t < 8 && t < emax) {
            ii_s[t] = g_ei[e0 + t];
            jj_s[t] = g_ej[e0 + t];
            env_s[t] = g_env[e0 + t];
        }
        if (t < 24 && (t / 3) < emax) unit_s[t] = g_unit[e0 * 3 + t];
        for (int x = t; x < 160; x += 128)
            if ((x / 20) < emax) rbf_s[x] = g_rbf[e0 * 20 + x];
        __syncthreads();

        #pragma unroll
        for (int e = 0; e < 8; e++) {
            if (e < emax) {
                int j = jj_s[e];
                float ws0 = br0, ws1 = br1, ws2 = br2;
                #pragma unroll
                for (int k = 0; k < 20; k++) {
                    float rv = rbf_s[e * 20 + k];
                    ws0 += rv * wr[k];
                    ws1 += rv * wr[20 + k];
                    ws2 += rv * wr[40 + k];
                }
                float env = env_s[e];
                const float* pj = phi + j * 384;
                float ds = pj[t]       * ws0 * env;
                float gv = pj[128 + t] * ws1 * env;
                float gu = pj[256 + t] * ws2 * env;
                const float* vj = v_in + j * 384 + 3 * t;
                float ux = unit_s[3 * e], uy = unit_s[3 * e + 1], uz = unit_s[3 * e + 2];
                prod_s[e * 512 + t]             = ds;
                prod_s[e * 512 + 128 + 3 * t]     = gu * ux + gv * vj[0];
                prod_s[e * 512 + 128 + 3 * t + 1] = gu * uy + gv * vj[1];
                prod_s[e * 512 + 128 + 3 * t + 2] = gu * uz + gv * vj[2];
            }
        }
        __syncthreads();

        #pragma unroll
        for (int e = 0; e < 8; e++) {
            if (e < emax) {
                int node = ii_s[e];
                const float4 val = *reinterpret_cast<const float4*>(&prod_s[e * 512 + t * 4]);
                float* dst = (t < 32) ? (s_acc + node * 128 + t * 4)
                                      : (v_acc + node * 384 + (t - 32) * 4);
                red4(dst, val.x, val.y, val.z, val.w);
            }
        }
        __syncthreads();
    }
}

// ---------------- orchestration -------------------------------------------
extern "C" void kernel_launch(void* const* d_in, const int* in_sizes, int n_in,
                              void* d_out, int out_size) {
    (void)in_sizes; (void)n_in; (void)out_size;
    const float* xyz  = (const float*)d_in[0];
    const int*   nbr  = (const int*)d_in[1];
    const float* cg_s = (const float*)d_in[2];
    const float* W1   = (const float*)d_in[3];
    const float* b1   = (const float*)d_in[4];
    const float* W2   = (const float*)d_in[5];
    const float* b2   = (const float*)d_in[6];
    const float* Wr   = (const float*)d_in[7];
    const float* brr  = (const float*)d_in[8];
    float* s_out = (float*)d_out;                       // (N,128)
    float* v_out_final = s_out + (size_t)NN * 128;      // (N,128,3)

    void *p_count, *p_h, *p_phi, *p_vz, *p_va, *p_vb;
    cudaGetSymbolAddress(&p_count, g_count);
    cudaGetSymbolAddress(&p_h, g_h);
    cudaGetSymbolAddress(&p_phi, g_phi);
    cudaGetSymbolAddress(&p_vz, g_vz);
    cudaGetSymbolAddress(&p_va, g_va);
    cudaGetSymbolAddress(&p_vb, g_vb);

    size_t vbytes = (size_t)NN * 384 * sizeof(float);
    cudaMemsetAsync(p_count, 0, sizeof(int));
    cudaMemsetAsync(p_vz, 0, vbytes);
    cudaMemsetAsync(p_va, 0, vbytes);
    cudaMemcpyAsync(s_out, cg_s, (size_t)NN * 128 * sizeof(float),
                    cudaMemcpyDeviceToDevice);

    precompute_kernel<<<(NE + 127) / 128, 128>>>(xyz, nbr);

    const float* vin[3] = {(const float*)p_vz, (const float*)p_va, (const float*)p_vb};
    float* vout[3] = {(float*)p_va, (float*)p_vb, v_out_final};

    dim3 g1((NN + 127) / 128, 1), g2((NN + 127) / 128, 3);
    for (int l = 0; l < 3; l++) {
        gemm_k128<1><<<g1, 256>>>(s_out, W1 + l * 128 * 128, b1 + l * 128,
                                  (float*)p_h, NN, 128);
        gemm_k128<0><<<g2, 256>>>((const float*)p_h, W2 + l * 128 * 384,
                                  b2 + l * 384, (float*)p_phi, NN, 384);
        if (l == 1) cudaMemcpyAsync(p_vb, p_va, vbytes, cudaMemcpyDeviceToDevice);
        if (l == 2) cudaMemcpyAsync(v_out_final, p_vb, vbytes, cudaMemcpyDeviceToDevice);
        edge_kernel<<<1480, 128>>>((const float*)p_phi, vin[l], s_out, vout[l],
                                   Wr + l * 20 * 384, brr + l * 384);
    }
}